// round 4
// baseline (speedup 1.0000x reference)
#include <cuda_runtime.h>
#include <cstdint>

#define N_NODES 50000
#define N_EDGES 600000
#define D 128
#define DE 32

// Scratch (static device globals — no runtime allocation allowed)
__device__ int   g_src[N_EDGES];
__device__ int   g_dst[N_EDGES];
__device__ float g_bufA[N_NODES * D];
__device__ float g_bufB[N_NODES * D];
__device__ float g_bufC[N_NODES * D];
__device__ int   g_is64;

// ---------------------------------------------------------------------------
// edge_index dtype detection: if the data is int64 (values < 2^31), every
// odd int32 word (the high halves) is zero. If genuinely int32 random in
// [0, 50000), the probability all sampled odd words are zero is ~0.
// ---------------------------------------------------------------------------
__global__ void detect_kernel(const int* __restrict__ p, int n_words) {
    if (threadIdx.x == 0 && blockIdx.x == 0) {
        int all0 = 1;
        int lim = n_words / 2 < 64 ? n_words / 2 : 64;
        for (int i = 0; i < lim; i++) {
            if (p[2 * i + 1] != 0) { all0 = 0; break; }
        }
        g_is64 = all0;
    }
}

__global__ void convert_kernel(const void* __restrict__ eidx) {
    int e = blockIdx.x * blockDim.x + threadIdx.x;
    if (e >= N_EDGES) return;
    if (g_is64) {
        const long long* p = (const long long*)eidx;
        g_src[e] = (int)p[e];
        g_dst[e] = (int)p[N_EDGES + e];
    } else {
        const int* p = (const int*)eidx;
        g_src[e] = p[e];
        g_dst[e] = p[N_EDGES + e];
    }
}

__global__ void copy_kernel(const float4* __restrict__ src, float4* __restrict__ dst, int n4) {
    int i = blockIdx.x * blockDim.x + threadIdx.x;
    if (i < n4) dst[i] = src[i];
}

// ---------------------------------------------------------------------------
// Edge kernel: one warp per edge (grid-stride).
//   emb = edge_attr[e] @ we + be          (32x128 mini-GEMM, we in smem)
//   msg = relu(X[src] + emb)
//   agg[dst] += msg                        (red.global.add.v4.f32)
// ---------------------------------------------------------------------------
__global__ void __launch_bounds__(256) edge_kernel(
    const float* __restrict__ X, const float* __restrict__ ea,
    const float* __restrict__ we, const float* __restrict__ be,
    float* __restrict__ agg)
{
    __shared__ float s_we[DE * D];
    __shared__ float s_be[D];
    __shared__ float s_ea[8][DE];

    int tid = threadIdx.x;
    for (int i = tid; i < DE * D / 4; i += 256)
        ((float4*)s_we)[i] = ((const float4*)we)[i];
    if (tid < D) s_be[tid] = be[tid];
    __syncthreads();

    int lane = tid & 31;
    int w    = tid >> 5;
    int gw   = blockIdx.x * 8 + w;
    int stride = gridDim.x * 8;

    const float4* s_we4 = (const float4*)s_we;
    float4 bias = ((const float4*)s_be)[lane];

    for (int e = gw; e < N_EDGES; e += stride) {
        // stage this edge's 32 attrs into warp-private smem for broadcast reads
        s_ea[w][lane] = ea[(size_t)e * DE + lane];
        __syncwarp();

        float4 acc = bias;
        #pragma unroll
        for (int k = 0; k < DE; k++) {
            float a   = s_ea[w][k];
            float4 wv = s_we4[k * 32 + lane];
            acc.x = fmaf(a, wv.x, acc.x);
            acc.y = fmaf(a, wv.y, acc.y);
            acc.z = fmaf(a, wv.z, acc.z);
            acc.w = fmaf(a, wv.w, acc.w);
        }

        int src = g_src[e];
        int dst = g_dst[e];
        float4 xv = ((const float4*)X)[src * 32 + lane];
        float mx = fmaxf(acc.x + xv.x, 0.f);
        float my = fmaxf(acc.y + xv.y, 0.f);
        float mz = fmaxf(acc.z + xv.z, 0.f);
        float mw = fmaxf(acc.w + xv.w, 0.f);

        float* p = agg + (size_t)dst * D + lane * 4;
        asm volatile("red.global.add.v4.f32 [%0], {%1,%2,%3,%4};"
                     :: "l"(p), "f"(mx), "f"(my), "f"(mz), "f"(mw) : "memory");
        __syncwarp();  // protect s_ea before next iteration's overwrite
    }
}

// ---------------------------------------------------------------------------
// GEMM: C[N,128] = act(A[N,128] @ W[128,128] + b)
// 64-row tiles, 256 threads, 8x4 register micro-tile per thread.
// Dynamic smem: W (64KB) + A tile (32KB) = 96KB.
// ---------------------------------------------------------------------------
template<bool RELU>
__global__ void __launch_bounds__(256) gemm_kernel(
    const float* __restrict__ A, const float* __restrict__ W,
    const float* __restrict__ b, float* __restrict__ C)
{
    extern __shared__ float sm[];
    float* Ws = sm;             // [128][128]
    float* As = sm + D * D;     // [64][128]

    int tid = threadIdx.x;
    #pragma unroll
    for (int i = 0; i < 16; i++)
        ((float4*)Ws)[tid + i * 256] = ((const float4*)W)[tid + i * 256];

    int row0 = blockIdx.x * 64;
    #pragma unroll
    for (int i = 0; i < 8; i++) {
        int idx = tid + i * 256;        // float4 index within 64x32 tile
        int r   = idx >> 5;
        int c4  = idx & 31;
        int rg  = row0 + r;
        if (rg >= N_NODES) rg = N_NODES - 1;   // clamp (stores are guarded)
        ((float4*)As)[idx] = ((const float4*)A)[(size_t)rg * 32 + c4];
    }
    __syncthreads();

    int tx = tid & 31;   // column group: cols tx*4 .. tx*4+3
    int ty = tid >> 5;   // row group:   rows ty*8 .. ty*8+7

    float4 bv = ((const float4*)b)[tx];
    float4 acc[8];
    #pragma unroll
    for (int i = 0; i < 8; i++) acc[i] = bv;

    const float4* Ws4  = (const float4*)Ws;
    const float*  Arow = As + (ty * 8) * D;

    #pragma unroll 8
    for (int k = 0; k < D; k++) {
        float4 wv = Ws4[k * 32 + tx];
        #pragma unroll
        for (int i = 0; i < 8; i++) {
            float a = Arow[i * D + k];     // warp-uniform -> smem broadcast
            acc[i].x = fmaf(a, wv.x, acc[i].x);
            acc[i].y = fmaf(a, wv.y, acc[i].y);
            acc[i].z = fmaf(a, wv.z, acc[i].z);
            acc[i].w = fmaf(a, wv.w, acc[i].w);
        }
    }

    #pragma unroll
    for (int i = 0; i < 8; i++) {
        int rg = row0 + ty * 8 + i;
        if (rg < N_NODES) {
            float4 v = acc[i];
            if (RELU) {
                v.x = fmaxf(v.x, 0.f); v.y = fmaxf(v.y, 0.f);
                v.z = fmaxf(v.z, 0.f); v.w = fmaxf(v.w, 0.f);
            }
            ((float4*)C)[(size_t)rg * 32 + tx] = v;
        }
    }
}

// ---------------------------------------------------------------------------
static bool g_attr_done = false;

extern "C" void kernel_launch(void* const* d_in, const int* in_sizes, int n_in,
                              void* d_out, int out_size)
{
    const float* x     = (const float*)d_in[0];
    const void*  eidx  =               d_in[1];
    const float* ea    = (const float*)d_in[2];
    const float* w1_0  = (const float*)d_in[3];
    const float* b1_0  = (const float*)d_in[4];
    const float* w2_0  = (const float*)d_in[5];
    const float* b2_0  = (const float*)d_in[6];
    const float* we_0  = (const float*)d_in[7];
    const float* be_0  = (const float*)d_in[8];
    const float* w1_1  = (const float*)d_in[9];
    const float* b1_1  = (const float*)d_in[10];
    const float* w2_1  = (const float*)d_in[11];
    const float* b2_1  = (const float*)d_in[12];
    const float* we_1  = (const float*)d_in[13];
    const float* be_1  = (const float*)d_in[14];
    const float* fc1_w = (const float*)d_in[15];
    const float* fc1_b = (const float*)d_in[16];
    const float* fc2_w = (const float*)d_in[17];
    const float* fc2_b = (const float*)d_in[18];
    float* out = (float*)d_out;

    float *bufA, *bufB, *bufC;
    cudaGetSymbolAddress((void**)&bufA, g_bufA);
    cudaGetSymbolAddress((void**)&bufB, g_bufB);
    cudaGetSymbolAddress((void**)&bufC, g_bufC);

    const int SMEM = 96 * 1024;
    if (!g_attr_done) {
        cudaFuncSetAttribute((const void*)gemm_kernel<true>,
                             cudaFuncAttributeMaxDynamicSharedMemorySize, SMEM);
        cudaFuncSetAttribute((const void*)gemm_kernel<false>,
                             cudaFuncAttributeMaxDynamicSharedMemorySize, SMEM);
        g_attr_done = true;
    }

    // number of 32-bit words available in edge_index buffer (dtype-agnostic lower bound)
    int n_words = in_sizes[1];

    detect_kernel<<<1, 32>>>((const int*)eidx, n_words);
    convert_kernel<<<(N_EDGES + 255) / 256, 256>>>(eidx);

    int n4 = N_NODES * D / 4;
    int gb = (N_NODES + 63) / 64;

    // ----- layer 0 -----
    copy_kernel<<<(n4 + 255) / 256, 256>>>((const float4*)x, (float4*)bufA, n4);
    edge_kernel<<<1184, 256>>>(x, ea, we_0, be_0, bufA);
    gemm_kernel<true ><<<gb, 256, SMEM>>>(bufA, w1_0, b1_0, bufB);
    gemm_kernel<true ><<<gb, 256, SMEM>>>(bufB, w2_0, b2_0, bufC);  // fused post-layer ReLU

    // ----- layer 1 -----
    copy_kernel<<<(n4 + 255) / 256, 256>>>((const float4*)bufC, (float4*)bufA, n4);
    edge_kernel<<<1184, 256>>>(bufC, ea, we_1, be_1, bufA);
    gemm_kernel<true ><<<gb, 256, SMEM>>>(bufA, w1_1, b1_1, bufB);
    gemm_kernel<true ><<<gb, 256, SMEM>>>(bufB, w2_1, b2_1, bufC);  // fused post-layer ReLU

    // ----- head -----
    gemm_kernel<true ><<<gb, 256, SMEM>>>(bufC, fc1_w, fc1_b, bufB);
    gemm_kernel<false><<<gb, 256, SMEM>>>(bufB, fc2_w, fc2_b, out);
}

// round 5
// speedup vs baseline: 1.4523x; 1.4523x over previous
#include <cuda_runtime.h>
#include <cstdint>

#define N_NODES 50000
#define N_EDGES 600000
#define D 128
#define DE 32

// Scratch (static device globals — no runtime allocation allowed)
__device__ int   g_src[N_EDGES];
__device__ int   g_dst[N_EDGES];
__device__ float g_bufA[N_NODES * D];
__device__ float g_bufB[N_NODES * D];
__device__ float g_bufC[N_NODES * D];
__device__ int   g_is64;

// ---------------------------------------------------------------------------
// edge_index dtype detection (int64 high words all zero => int64)
// ---------------------------------------------------------------------------
__global__ void detect_kernel(const int* __restrict__ p, int n_words) {
    if (threadIdx.x == 0 && blockIdx.x == 0) {
        int all0 = 1;
        int lim = n_words / 2 < 64 ? n_words / 2 : 64;
        for (int i = 0; i < lim; i++) {
            if (p[2 * i + 1] != 0) { all0 = 0; break; }
        }
        g_is64 = all0;
    }
}

__global__ void convert_kernel(const void* __restrict__ eidx) {
    int e = blockIdx.x * blockDim.x + threadIdx.x;
    if (e >= N_EDGES) return;
    if (g_is64) {
        const long long* p = (const long long*)eidx;
        g_src[e] = (int)p[e];
        g_dst[e] = (int)p[N_EDGES + e];
    } else {
        const int* p = (const int*)eidx;
        g_src[e] = p[e];
        g_dst[e] = p[N_EDGES + e];
    }
}

__global__ void copy_kernel(const float4* __restrict__ src, float4* __restrict__ dst, int n4) {
    int i = blockIdx.x * blockDim.x + threadIdx.x;
    if (i < n4) dst[i] = src[i];
}

// ---------------------------------------------------------------------------
// Edge kernel v2: 8 edges per warp per batch.
// The we[32][128] weight rows are read ONCE per 8 edges (amortized), cutting
// smem phase count per edge ~6.7x vs the v1 per-edge mini-GEMM.
//   emb_i = ea[e_i] @ we + be
//   msg_i = relu(X[src_i] + emb_i)
//   agg[dst_i] += msg_i   (red.global.add.v4.f32)
// ---------------------------------------------------------------------------
__global__ void __launch_bounds__(256) edge_kernel(
    const float* __restrict__ X, const float* __restrict__ ea,
    const float* __restrict__ we, const float* __restrict__ be,
    float* __restrict__ agg)
{
    __shared__ float  s_we[DE * D];        // 16 KB
    __shared__ float4 s_ea[8][8][8];       // [warp][edge][k4]  8 KB

    int tid  = threadIdx.x;
    int lane = tid & 31;
    int w    = tid >> 5;

    for (int i = tid; i < DE * D / 4; i += 256)
        ((float4*)s_we)[i] = ((const float4*)we)[i];
    __syncthreads();

    const float4* s_we4 = (const float4*)s_we;
    float4 bias = ((const float4*)be)[lane];    // hoisted, L1-cached

    int gw     = blockIdx.x * 8 + w;
    int nwarp  = gridDim.x * 8;
    int nbatch = N_EDGES / 8;                   // 75000, exact

    for (int batch = gw; batch < nbatch; batch += nwarp) {
        int e0 = batch * 8;

        // stage 8 edges x 32 attrs = 64 float4 (coalesced)
        float4* sw = &s_ea[w][0][0];
        #pragma unroll
        for (int p = 0; p < 2; p++) {
            int idx = p * 32 + lane;                       // edge = idx>>3, k4 = idx&7
            sw[idx] = ((const float4*)ea)[(size_t)e0 * 8 + idx];
        }
        __syncwarp();

        float4 acc[8];
        #pragma unroll
        for (int i = 0; i < 8; i++) acc[i] = bias;

        #pragma unroll
        for (int k4 = 0; k4 < 8; k4++) {
            // 4 weight rows (k = k4*4 .. k4*4+3), this lane's 4 output cols
            float4 wv0 = s_we4[(k4 * 4 + 0) * 32 + lane];
            float4 wv1 = s_we4[(k4 * 4 + 1) * 32 + lane];
            float4 wv2 = s_we4[(k4 * 4 + 2) * 32 + lane];
            float4 wv3 = s_we4[(k4 * 4 + 3) * 32 + lane];
            #pragma unroll
            for (int i = 0; i < 8; i++) {
                float4 a = s_ea[w][i][k4];     // warp-uniform broadcast
                acc[i].x = fmaf(a.x, wv0.x, acc[i].x);
                acc[i].y = fmaf(a.x, wv0.y, acc[i].y);
                acc[i].z = fmaf(a.x, wv0.z, acc[i].z);
                acc[i].w = fmaf(a.x, wv0.w, acc[i].w);
                acc[i].x = fmaf(a.y, wv1.x, acc[i].x);
                acc[i].y = fmaf(a.y, wv1.y, acc[i].y);
                acc[i].z = fmaf(a.y, wv1.z, acc[i].z);
                acc[i].w = fmaf(a.y, wv1.w, acc[i].w);
                acc[i].x = fmaf(a.z, wv2.x, acc[i].x);
                acc[i].y = fmaf(a.z, wv2.y, acc[i].y);
                acc[i].z = fmaf(a.z, wv2.z, acc[i].z);
                acc[i].w = fmaf(a.z, wv2.w, acc[i].w);
                acc[i].x = fmaf(a.w, wv3.x, acc[i].x);
                acc[i].y = fmaf(a.w, wv3.y, acc[i].y);
                acc[i].z = fmaf(a.w, wv3.z, acc[i].z);
                acc[i].w = fmaf(a.w, wv3.w, acc[i].w);
            }
        }

        // gather + relu + scatter-add, one edge at a time (row ops coalesced)
        #pragma unroll
        for (int i = 0; i < 8; i++) {
            int src = g_src[e0 + i];           // warp-uniform load
            int dst = g_dst[e0 + i];
            float4 xv = ((const float4*)X)[(size_t)src * 32 + lane];
            float mx = fmaxf(acc[i].x + xv.x, 0.f);
            float my = fmaxf(acc[i].y + xv.y, 0.f);
            float mz = fmaxf(acc[i].z + xv.z, 0.f);
            float mw = fmaxf(acc[i].w + xv.w, 0.f);
            float* p = agg + (size_t)dst * D + lane * 4;
            asm volatile("red.global.add.v4.f32 [%0], {%1,%2,%3,%4};"
                         :: "l"(p), "f"(mx), "f"(my), "f"(mz), "f"(mw) : "memory");
        }
        __syncwarp();   // protect s_ea before next batch restage
    }
}

// ---------------------------------------------------------------------------
// GEMM: C[N,128] = act(A[N,128] @ W[128,128] + b)   (unchanged from v1)
// ---------------------------------------------------------------------------
template<bool RELU>
__global__ void __launch_bounds__(256) gemm_kernel(
    const float* __restrict__ A, const float* __restrict__ W,
    const float* __restrict__ b, float* __restrict__ C)
{
    extern __shared__ float sm[];
    float* Ws = sm;             // [128][128]
    float* As = sm + D * D;     // [64][128]

    int tid = threadIdx.x;
    #pragma unroll
    for (int i = 0; i < 16; i++)
        ((float4*)Ws)[tid + i * 256] = ((const float4*)W)[tid + i * 256];

    int row0 = blockIdx.x * 64;
    #pragma unroll
    for (int i = 0; i < 8; i++) {
        int idx = tid + i * 256;
        int r   = idx >> 5;
        int c4  = idx & 31;
        int rg  = row0 + r;
        if (rg >= N_NODES) rg = N_NODES - 1;
        ((float4*)As)[idx] = ((const float4*)A)[(size_t)rg * 32 + c4];
    }
    __syncthreads();

    int tx = tid & 31;
    int ty = tid >> 5;

    float4 bv = ((const float4*)b)[tx];
    float4 acc[8];
    #pragma unroll
    for (int i = 0; i < 8; i++) acc[i] = bv;

    const float4* Ws4  = (const float4*)Ws;
    const float*  Arow = As + (ty * 8) * D;

    #pragma unroll 8
    for (int k = 0; k < D; k++) {
        float4 wv = Ws4[k * 32 + tx];
        #pragma unroll
        for (int i = 0; i < 8; i++) {
            float a = Arow[i * D + k];
            acc[i].x = fmaf(a, wv.x, acc[i].x);
            acc[i].y = fmaf(a, wv.y, acc[i].y);
            acc[i].z = fmaf(a, wv.z, acc[i].z);
            acc[i].w = fmaf(a, wv.w, acc[i].w);
        }
    }

    #pragma unroll
    for (int i = 0; i < 8; i++) {
        int rg = row0 + ty * 8 + i;
        if (rg < N_NODES) {
            float4 v = acc[i];
            if (RELU) {
                v.x = fmaxf(v.x, 0.f); v.y = fmaxf(v.y, 0.f);
                v.z = fmaxf(v.z, 0.f); v.w = fmaxf(v.w, 0.f);
            }
            ((float4*)C)[(size_t)rg * 32 + tx] = v;
        }
    }
}

// ---------------------------------------------------------------------------
static bool g_attr_done = false;

extern "C" void kernel_launch(void* const* d_in, const int* in_sizes, int n_in,
                              void* d_out, int out_size)
{
    const float* x     = (const float*)d_in[0];
    const void*  eidx  =               d_in[1];
    const float* ea    = (const float*)d_in[2];
    const float* w1_0  = (const float*)d_in[3];
    const float* b1_0  = (const float*)d_in[4];
    const float* w2_0  = (const float*)d_in[5];
    const float* b2_0  = (const float*)d_in[6];
    const float* we_0  = (const float*)d_in[7];
    const float* be_0  = (const float*)d_in[8];
    const float* w1_1  = (const float*)d_in[9];
    const float* b1_1  = (const float*)d_in[10];
    const float* w2_1  = (const float*)d_in[11];
    const float* b2_1  = (const float*)d_in[12];
    const float* we_1  = (const float*)d_in[13];
    const float* be_1  = (const float*)d_in[14];
    const float* fc1_w = (const float*)d_in[15];
    const float* fc1_b = (const float*)d_in[16];
    const float* fc2_w = (const float*)d_in[17];
    const float* fc2_b = (const float*)d_in[18];
    float* out = (float*)d_out;

    float *bufA, *bufB, *bufC;
    cudaGetSymbolAddress((void**)&bufA, g_bufA);
    cudaGetSymbolAddress((void**)&bufB, g_bufB);
    cudaGetSymbolAddress((void**)&bufC, g_bufC);

    const int SMEM = 96 * 1024;
    if (!g_attr_done) {
        cudaFuncSetAttribute((const void*)gemm_kernel<true>,
                             cudaFuncAttributeMaxDynamicSharedMemorySize, SMEM);
        cudaFuncSetAttribute((const void*)gemm_kernel<false>,
                             cudaFuncAttributeMaxDynamicSharedMemorySize, SMEM);
        g_attr_done = true;
    }

    int n_words = in_sizes[1];

    detect_kernel<<<1, 32>>>((const int*)eidx, n_words);
    convert_kernel<<<(N_EDGES + 255) / 256, 256>>>(eidx);

    int n4 = N_NODES * D / 4;
    int gb = (N_NODES + 63) / 64;

    // ----- layer 0 -----
    copy_kernel<<<(n4 + 255) / 256, 256>>>((const float4*)x, (float4*)bufA, n4);
    edge_kernel<<<1184, 256>>>(x, ea, we_0, be_0, bufA);
    gemm_kernel<true ><<<gb, 256, SMEM>>>(bufA, w1_0, b1_0, bufB);
    gemm_kernel<true ><<<gb, 256, SMEM>>>(bufB, w2_0, b2_0, bufC);  // fused post-layer ReLU

    // ----- layer 1 -----
    copy_kernel<<<(n4 + 255) / 256, 256>>>((const float4*)bufC, (float4*)bufA, n4);
    edge_kernel<<<1184, 256>>>(bufC, ea, we_1, be_1, bufA);
    gemm_kernel<true ><<<gb, 256, SMEM>>>(bufA, w1_1, b1_1, bufB);
    gemm_kernel<true ><<<gb, 256, SMEM>>>(bufB, w2_1, b2_1, bufC);  // fused post-layer ReLU

    // ----- head -----
    gemm_kernel<true ><<<gb, 256, SMEM>>>(bufC, fc1_w, fc1_b, bufB);
    gemm_kernel<false><<<gb, 256, SMEM>>>(bufB, fc2_w, fc2_b, out);
}

// round 7
// speedup vs baseline: 1.8657x; 1.2846x over previous
#include <cuda_runtime.h>
#include <cuda_bf16.h>
#include <cstdint>

#define N_NODES 50000
#define N_EDGES 600000
#define D 128
#define DE 32

// ---------------------------------------------------------------------------
// Scratch (static device globals — no runtime allocation allowed)
// ---------------------------------------------------------------------------
__device__ int   g_src[N_EDGES];
__device__ int   g_dst[N_EDGES];
__device__ float g_bufA[N_NODES * D];
__device__ float g_bufB[N_NODES * D];
__device__ float g_bufC[N_NODES * D];
__device__ int   g_is64;
// pre-split, pre-swizzled weights: [6 weights][128x128 bf16] (B-operand layout)
__device__ __nv_bfloat16 g_whi[6][D * D];
__device__ __nv_bfloat16 g_wlo[6][D * D];

// ---------------------------------------------------------------------------
// helpers
// ---------------------------------------------------------------------------
__device__ __forceinline__ uint32_t smem_to_u32(const void* p) {
    uint32_t a;
    asm("{ .reg .u64 t; cvta.to.shared.u64 t, %1; cvt.u32.u64 %0, t; }" : "=r"(a) : "l"(p));
    return a;
}

// byte offset inside a [128 rows x 128 cols] bf16 plane, row stride 256B,
// 16B chunks XOR-swizzled by (row & 7) -> conflict-free ldmatrix.
__device__ __host__ __forceinline__ uint32_t sw_off(int row, int col) {
    return (uint32_t)row * 256u + (uint32_t)(((col >> 3) ^ (row & 7)) << 4)
         + (uint32_t)(col & 7) * 2u;
}

__device__ __forceinline__ void ldsm4(uint32_t* r, uint32_t addr) {
    asm volatile("ldmatrix.sync.aligned.m8n8.x4.shared.b16 {%0,%1,%2,%3}, [%4];"
                 : "=r"(r[0]), "=r"(r[1]), "=r"(r[2]), "=r"(r[3]) : "r"(addr));
}

__device__ __forceinline__ void mma_bf16(float* d, const uint32_t* a, const uint32_t* b) {
    asm volatile("mma.sync.aligned.m16n8k16.row.col.f32.bf16.bf16.f32 "
                 "{%0,%1,%2,%3}, {%4,%5,%6,%7}, {%8,%9}, {%0,%1,%2,%3};"
                 : "+f"(d[0]), "+f"(d[1]), "+f"(d[2]), "+f"(d[3])
                 : "r"(a[0]), "r"(a[1]), "r"(a[2]), "r"(a[3]), "r"(b[0]), "r"(b[1]));
}

// ---------------------------------------------------------------------------
// edge_index dtype detection (int64 high words all zero => int64)
// ---------------------------------------------------------------------------
__global__ void detect_kernel(const int* __restrict__ p, int n_words) {
    if (threadIdx.x == 0 && blockIdx.x == 0) {
        int all0 = 1;
        int lim = n_words / 2 < 64 ? n_words / 2 : 64;
        for (int i = 0; i < lim; i++) {
            if (p[2 * i + 1] != 0) { all0 = 0; break; }
        }
        g_is64 = all0;
    }
}

__global__ void convert_kernel(const void* __restrict__ eidx) {
    int e = blockIdx.x * blockDim.x + threadIdx.x;
    if (e >= N_EDGES) return;
    if (g_is64) {
        const long long* p = (const long long*)eidx;
        g_src[e] = (int)p[e];
        g_dst[e] = (int)p[N_EDGES + e];
    } else {
        const int* p = (const int*)eidx;
        g_src[e] = p[e];
        g_dst[e] = p[N_EDGES + e];
    }
}

__global__ void copy_kernel(const float4* __restrict__ src, float4* __restrict__ dst, int n4) {
    int i = blockIdx.x * blockDim.x + threadIdx.x;
    if (i < n4) dst[i] = src[i];
}

// ---------------------------------------------------------------------------
// Weight pre-split: W[k][n] fp32 -> hi/lo bf16 planes in B-operand layout
// ([n][k] rows, swizzled), so GEMM CTAs copy linearly into smem.
// ---------------------------------------------------------------------------
__global__ void wsplit_kernel(const float* __restrict__ W,
                              __nv_bfloat16* __restrict__ whi,
                              __nv_bfloat16* __restrict__ wlo) {
    int idx = blockIdx.x * blockDim.x + threadIdx.x;
    if (idx >= D * D) return;
    int n = idx >> 7;
    int k = idx & 127;
    float w = W[k * D + n];
    __nv_bfloat16 hi = __float2bfloat16(w);
    __nv_bfloat16 lo = __float2bfloat16(w - __bfloat162float(hi));
    uint32_t off = sw_off(n, k);
    *(__nv_bfloat16*)((char*)whi + off) = hi;
    *(__nv_bfloat16*)((char*)wlo + off) = lo;
}

// ---------------------------------------------------------------------------
// Edge kernel (unchanged, at its fp32 roofline): 8 edges per warp per batch.
// ---------------------------------------------------------------------------
__global__ void __launch_bounds__(256) edge_kernel(
    const float* __restrict__ X, const float* __restrict__ ea,
    const float* __restrict__ we, const float* __restrict__ be,
    float* __restrict__ agg)
{
    __shared__ float  s_we[DE * D];
    __shared__ float4 s_ea[8][8][8];

    int tid  = threadIdx.x;
    int lane = tid & 31;
    int w    = tid >> 5;

    for (int i = tid; i < DE * D / 4; i += 256)
        ((float4*)s_we)[i] = ((const float4*)we)[i];
    __syncthreads();

    const float4* s_we4 = (const float4*)s_we;
    float4 bias = ((const float4*)be)[lane];

    int gw     = blockIdx.x * 8 + w;
    int nwarp  = gridDim.x * 8;
    int nbatch = N_EDGES / 8;

    for (int batch = gw; batch < nbatch; batch += nwarp) {
        int e0 = batch * 8;

        float4* sw = &s_ea[w][0][0];
        #pragma unroll
        for (int p = 0; p < 2; p++) {
            int idx = p * 32 + lane;
            sw[idx] = ((const float4*)ea)[(size_t)e0 * 8 + idx];
        }
        __syncwarp();

        float4 acc[8];
        #pragma unroll
        for (int i = 0; i < 8; i++) acc[i] = bias;

        #pragma unroll
        for (int k4 = 0; k4 < 8; k4++) {
            float4 wv0 = s_we4[(k4 * 4 + 0) * 32 + lane];
            float4 wv1 = s_we4[(k4 * 4 + 1) * 32 + lane];
            float4 wv2 = s_we4[(k4 * 4 + 2) * 32 + lane];
            float4 wv3 = s_we4[(k4 * 4 + 3) * 32 + lane];
            #pragma unroll
            for (int i = 0; i < 8; i++) {
                float4 a = s_ea[w][i][k4];
                acc[i].x = fmaf(a.x, wv0.x, acc[i].x);
                acc[i].y = fmaf(a.x, wv0.y, acc[i].y);
                acc[i].z = fmaf(a.x, wv0.z, acc[i].z);
                acc[i].w = fmaf(a.x, wv0.w, acc[i].w);
                acc[i].x = fmaf(a.y, wv1.x, acc[i].x);
                acc[i].y = fmaf(a.y, wv1.y, acc[i].y);
                acc[i].z = fmaf(a.y, wv1.z, acc[i].z);
                acc[i].w = fmaf(a.y, wv1.w, acc[i].w);
                acc[i].x = fmaf(a.z, wv2.x, acc[i].x);
                acc[i].y = fmaf(a.z, wv2.y, acc[i].y);
                acc[i].z = fmaf(a.z, wv2.z, acc[i].z);
                acc[i].w = fmaf(a.z, wv2.w, acc[i].w);
                acc[i].x = fmaf(a.w, wv3.x, acc[i].x);
                acc[i].y = fmaf(a.w, wv3.y, acc[i].y);
                acc[i].z = fmaf(a.w, wv3.z, acc[i].z);
                acc[i].w = fmaf(a.w, wv3.w, acc[i].w);
            }
        }

        #pragma unroll
        for (int i = 0; i < 8; i++) {
            int src = g_src[e0 + i];
            int dst = g_dst[e0 + i];
            float4 xv = ((const float4*)X)[(size_t)src * 32 + lane];
            float mx = fmaxf(acc[i].x + xv.x, 0.f);
            float my = fmaxf(acc[i].y + xv.y, 0.f);
            float mz = fmaxf(acc[i].z + xv.z, 0.f);
            float mw = fmaxf(acc[i].w + xv.w, 0.f);
            float* p = agg + (size_t)dst * D + lane * 4;
            asm volatile("red.global.add.v4.f32 [%0], {%1,%2,%3,%4};"
                         :: "l"(p), "f"(mx), "f"(my), "f"(mz), "f"(mw) : "memory");
        }
        __syncwarp();
    }
}

// ---------------------------------------------------------------------------
// HMMA GEMM: C[N_NODES,128] = act(A @ W + b), bf16 hi/lo split (3 cross terms)
// via mma.sync.m16n8k16. CTA = 256 thr / 8 warps, M-tile 128.
// Dyn smem: A-hi, A-lo, B-hi, B-lo planes, 32KB each = 128KB.
// ---------------------------------------------------------------------------
static constexpr int OFF_AHI = 0;
static constexpr int OFF_ALO = 32768;
static constexpr int OFF_BHI = 2 * 32768;
static constexpr int OFF_BLO = 3 * 32768;
static constexpr int SMEM_MMA = 4 * 32768;   // 128 KB

template<bool RELU>
__global__ void __launch_bounds__(256) gemm_mma(
    const float* __restrict__ A,
    const __nv_bfloat16* __restrict__ Whi, const __nv_bfloat16* __restrict__ Wlo,
    const float* __restrict__ b, float* __restrict__ C)
{
    extern __shared__ char sm[];
    uint32_t smem_base = smem_to_u32(sm);
    int tid  = threadIdx.x;
    int lane = tid & 31;
    int wid  = tid >> 5;

    // --- stage B planes (pre-split + pre-swizzled): linear uint4 copy ---
    {
        const uint4* hg = (const uint4*)Whi;
        const uint4* lg = (const uint4*)Wlo;
        uint4* hs = (uint4*)(sm + OFF_BHI);
        uint4* ls = (uint4*)(sm + OFF_BLO);
        #pragma unroll
        for (int i = 0; i < 8; i++) {
            hs[tid + i * 256] = hg[tid + i * 256];
            ls[tid + i * 256] = lg[tid + i * 256];
        }
    }

    // --- stage A: load fp32, split hi/lo bf16, store swizzled ---
    int row0 = blockIdx.x * 128;
    #pragma unroll
    for (int i = 0; i < 16; i++) {
        int idx = tid + i * 256;        // float4 index in 128x32 tile
        int row = idx >> 5;
        int c4  = idx & 31;
        int rg  = row0 + row;
        if (rg >= N_NODES) rg = N_NODES - 1;
        float4 v = ((const float4*)A)[(size_t)rg * 32 + c4];

        __nv_bfloat16 hx = __float2bfloat16(v.x), hy = __float2bfloat16(v.y);
        __nv_bfloat16 hz = __float2bfloat16(v.z), hw = __float2bfloat16(v.w);
        __nv_bfloat16 lx = __float2bfloat16(v.x - __bfloat162float(hx));
        __nv_bfloat16 ly = __float2bfloat16(v.y - __bfloat162float(hy));
        __nv_bfloat16 lz = __float2bfloat16(v.z - __bfloat162float(hz));
        __nv_bfloat16 lw = __float2bfloat16(v.w - __bfloat162float(hw));

        uint32_t h01 = ((uint32_t)__bfloat16_as_ushort(hy) << 16) | __bfloat16_as_ushort(hx);
        uint32_t h23 = ((uint32_t)__bfloat16_as_ushort(hw) << 16) | __bfloat16_as_ushort(hz);
        uint32_t l01 = ((uint32_t)__bfloat16_as_ushort(ly) << 16) | __bfloat16_as_ushort(lx);
        uint32_t l23 = ((uint32_t)__bfloat16_as_ushort(lw) << 16) | __bfloat16_as_ushort(lz);

        uint32_t off = sw_off(row, c4 * 4);   // 8B-aligned (col%8 in {0,4})
        *(uint2*)(sm + OFF_AHI + off) = make_uint2(h01, h23);
        *(uint2*)(sm + OFF_ALO + off) = make_uint2(l01, l23);
    }
    __syncthreads();

    // --- accumulators, bias folded in ---
    // acc[nt]: c0,c1 = (row lane>>2, cols nt*8+(lane%4)*2 +{0,1}); c2,c3 = row+8
    float acc[16][4];
    #pragma unroll
    for (int nt = 0; nt < 16; nt++) {
        float2 bv = *(const float2*)(b + nt * 8 + (lane & 3) * 2);
        acc[nt][0] = bv.x; acc[nt][1] = bv.y;
        acc[nt][2] = bv.x; acc[nt][3] = bv.y;
    }

    // ldmatrix lane->address mapping
    int am = lane >> 3;                           // A: matrix id 0..3
    int arow = wid * 16 + (lane & 7) + (am & 1) * 8;
    int achunkoff = am >> 1;
    int brow_loc  = ((lane >> 4) << 3) + (lane & 7);  // B: local n row 0..15
    int bchunkoff = (lane >> 3) & 1;

    uint32_t aHi = smem_base + OFF_AHI, aLo = smem_base + OFF_ALO;
    uint32_t bHi = smem_base + OFF_BHI, bLo = smem_base + OFF_BLO;

    #pragma unroll
    for (int ks = 0; ks < 8; ks++) {
        uint32_t ah[4], al[4];
        int achunk = ks * 2 + achunkoff;
        uint32_t aoff = (uint32_t)arow * 256u + (uint32_t)((achunk ^ (arow & 7)) << 4);
        ldsm4(ah, aHi + aoff);
        ldsm4(al, aLo + aoff);
        #pragma unroll
        for (int np = 0; np < 8; np++) {
            int brow = np * 16 + brow_loc;
            int bchunk = ks * 2 + bchunkoff;
            uint32_t boff = (uint32_t)brow * 256u + (uint32_t)((bchunk ^ (brow & 7)) << 4);
            uint32_t bh[4], bl[4];
            ldsm4(bh, bHi + boff);
            ldsm4(bl, bLo + boff);
            mma_bf16(acc[2 * np + 0], ah, bh + 0);
            mma_bf16(acc[2 * np + 1], ah, bh + 2);
            mma_bf16(acc[2 * np + 0], ah, bl + 0);
            mma_bf16(acc[2 * np + 1], ah, bl + 2);
            mma_bf16(acc[2 * np + 0], al, bh + 0);
            mma_bf16(acc[2 * np + 1], al, bh + 2);
        }
    }

    // --- epilogue: fused ReLU, float2 stores ---
    int r0 = row0 + wid * 16 + (lane >> 2);
    int r1 = r0 + 8;
    int cb = (lane & 3) * 2;
    #pragma unroll
    for (int nt = 0; nt < 16; nt++) {
        float2 v0 = make_float2(acc[nt][0], acc[nt][1]);
        float2 v1 = make_float2(acc[nt][2], acc[nt][3]);
        if (RELU) {
            v0.x = fmaxf(v0.x, 0.f); v0.y = fmaxf(v0.y, 0.f);
            v1.x = fmaxf(v1.x, 0.f); v1.y = fmaxf(v1.y, 0.f);
        }
        if (r0 < N_NODES) *(float2*)(C + (size_t)r0 * D + nt * 8 + cb) = v0;
        if (r1 < N_NODES) *(float2*)(C + (size_t)r1 * D + nt * 8 + cb) = v1;
    }
}

// ---------------------------------------------------------------------------
static bool g_attr_done = false;

extern "C" void kernel_launch(void* const* d_in, const int* in_sizes, int n_in,
                              void* d_out, int out_size)
{
    const float* x     = (const float*)d_in[0];
    const void*  eidx  =               d_in[1];
    const float* ea    = (const float*)d_in[2];
    const float* w1_0  = (const float*)d_in[3];
    const float* b1_0  = (const float*)d_in[4];
    const float* w2_0  = (const float*)d_in[5];
    const float* b2_0  = (const float*)d_in[6];
    const float* we_0  = (const float*)d_in[7];
    const float* be_0  = (const float*)d_in[8];
    const float* w1_1  = (const float*)d_in[9];
    const float* b1_1  = (const float*)d_in[10];
    const float* w2_1  = (const float*)d_in[11];
    const float* b2_1  = (const float*)d_in[12];
    const float* we_1  = (const float*)d_in[13];
    const float* be_1  = (const float*)d_in[14];
    const float* fc1_w = (const float*)d_in[15];
    const float* fc1_b = (const float*)d_in[16];
    const float* fc2_w = (const float*)d_in[17];
    const float* fc2_b = (const float*)d_in[18];
    float* out = (float*)d_out;

    float *bufA, *bufB, *bufC;
    __nv_bfloat16 *whi, *wlo;
    cudaGetSymbolAddress((void**)&bufA, g_bufA);
    cudaGetSymbolAddress((void**)&bufB, g_bufB);
    cudaGetSymbolAddress((void**)&bufC, g_bufC);
    cudaGetSymbolAddress((void**)&whi,  g_whi);
    cudaGetSymbolAddress((void**)&wlo,  g_wlo);

    if (!g_attr_done) {
        cudaFuncSetAttribute((const void*)gemm_mma<true>,
                             cudaFuncAttributeMaxDynamicSharedMemorySize, SMEM_MMA);
        cudaFuncSetAttribute((const void*)gemm_mma<false>,
                             cudaFuncAttributeMaxDynamicSharedMemorySize, SMEM_MMA);
        g_attr_done = true;
    }

    int n_words = in_sizes[1];
    detect_kernel<<<1, 32>>>((const int*)eidx, n_words);
    convert_kernel<<<(N_EDGES + 255) / 256, 256>>>(eidx);

    // pre-split the 6 node-GEMM weights into B-operand layout
    const float* Ws[6] = {w1_0, w2_0, w1_1, w2_1, fc1_w, fc2_w};
    for (int i = 0; i < 6; i++)
        wsplit_kernel<<<64, 256>>>(Ws[i], whi + i * D * D, wlo + i * D * D);

    int n4 = N_NODES * D / 4;
    int gt = (N_NODES + 127) / 128;   // 391 M-tiles

    // ----- layer 0 -----
    copy_kernel<<<(n4 + 255) / 256, 256>>>((const float4*)x, (float4*)bufA, n4);
    edge_kernel<<<1184, 256>>>(x, ea, we_0, be_0, bufA);
    gemm_mma<true ><<<gt, 256, SMEM_MMA>>>(bufA, whi + 0 * D * D, wlo + 0 * D * D, b1_0, bufB);
    gemm_mma<true ><<<gt, 256, SMEM_MMA>>>(bufB, whi + 1 * D * D, wlo + 1 * D * D, b2_0, bufC);

    // ----- layer 1 -----
    copy_kernel<<<(n4 + 255) / 256, 256>>>((const float4*)bufC, (float4*)bufA, n4);
    edge_kernel<<<1184, 256>>>(bufC, ea, we_1, be_1, bufA);
    gemm_mma<true ><<<gt, 256, SMEM_MMA>>>(bufA, whi + 2 * D * D, wlo + 2 * D * D, b1_1, bufB);
    gemm_mma<true ><<<gt, 256, SMEM_MMA>>>(bufB, whi + 3 * D * D, wlo + 3 * D * D, b2_1, bufC);

    // ----- head -----
    gemm_mma<true ><<<gt, 256, SMEM_MMA>>>(bufC, whi + 4 * D * D, wlo + 4 * D * D, fc1_b, bufB);
    gemm_mma<false><<<gt, 256, SMEM_MMA>>>(bufB, whi + 5 * D * D, wlo + 5 * D * D, fc2_b, out);
}